// round 5
// baseline (speedup 1.0000x reference)
#include <cuda_runtime.h>
#include <cuda_bf16.h>
#include <cstdint>

// ============================================================================
// GroupWiseLinearProjector via mma.sync bf16x3-split GEMM (compute_103-safe)
//   out[b,o,h,w] = sum_c x[b,c,h,w] * Wg[p(h,w),o,c],  p=(h%4)*4+(w%4)
// Per (b,phase): D[512 o, 256 px] = W[512,512] * X[256 px, 512]^T
// fp32 = bf16_hi + bf16_lo;  D = Wh*Xh + Wh*Xl + Wl*Xh  (fp32 accum)
// R5: 256x128 CTA tile, 512 threads (16 warps), KC=32/SW64, 4-stage cp.async,
//     coalesced g_tmp epilogue + separate unshuffle (R3 structure).
// ============================================================================

#define B_   16
#define CIN  512
#define COUT 512
#define NPX  256
#define KC   32          // K chunk (32 bf16 = 64B row, SW64 swizzle)
#define NSTAGE 16        // 512 / 32

// ---------------- scratch (device globals; no allocation) ----------------
__device__ __align__(256) unsigned short g_Xh[B_ * 16 * NPX * CIN];   // 64MB
__device__ __align__(256) unsigned short g_Xl[B_ * 16 * NPX * CIN];   // 64MB
__device__ __align__(256) unsigned short g_Wh[16 * COUT * CIN];       // 8MB
__device__ __align__(256) unsigned short g_Wl[16 * COUT * CIN];       // 8MB
__device__ __align__(256) float g_tmp[B_ * 16 * COUT * NPX];          // 134MB

// ---------------- helpers ----------------
__device__ __forceinline__ uint32_t smem_to_u32(const void* p) {
    uint32_t a;
    asm("{ .reg .u64 t; cvta.to.shared.u64 t, %1; cvt.u32.u64 %0, t; }"
        : "=r"(a) : "l"(p));
    return a;
}
__device__ __forceinline__ void cp_async16(uint32_t dst, const void* src) {
    asm volatile("cp.async.cg.shared.global [%0], [%1], 16;"
                 :: "r"(dst), "l"(src) : "memory");
}
#define CP_COMMIT() asm volatile("cp.async.commit_group;" ::: "memory")
#define CP_WAIT(n)  asm volatile("cp.async.wait_group %0;" :: "n"(n) : "memory")

__device__ __forceinline__ void ldmx4(uint32_t* r, uint32_t addr) {
    asm volatile("ldmatrix.sync.aligned.m8n8.x4.shared.b16 {%0,%1,%2,%3}, [%4];"
                 : "=r"(r[0]), "=r"(r[1]), "=r"(r[2]), "=r"(r[3]) : "r"(addr));
}
__device__ __forceinline__ void mma16816(float* d, const uint32_t* a,
                                         uint32_t b0, uint32_t b1) {
    asm volatile(
        "mma.sync.aligned.m16n8k16.row.col.f32.bf16.bf16.f32 "
        "{%0,%1,%2,%3}, {%4,%5,%6,%7}, {%8,%9}, {%0,%1,%2,%3};"
        : "+f"(d[0]), "+f"(d[1]), "+f"(d[2]), "+f"(d[3])
        : "r"(a[0]), "r"(a[1]), "r"(a[2]), "r"(a[3]), "r"(b0), "r"(b1));
}
// SW64 swizzle for 64B rows (8-row x 64B atom); key depends on row only.
#define SWZ64(off) ((uint32_t)(off) ^ ((((uint32_t)(off)) >> 3) & 0x30))

// ============================================================================
// Pass 1a: W -> Wh/Wl bf16 (same layout [ph][o][c])
// ============================================================================
__global__ __launch_bounds__(256)
void convert_w_kernel(const float* __restrict__ Wg) {
    size_t gt = (size_t)blockIdx.x * 256 + threadIdx.x;
    const float4* src = reinterpret_cast<const float4*>(Wg) + gt * 2;
    float4 a = src[0], b = src[1];
    float v[8] = {a.x, a.y, a.z, a.w, b.x, b.y, b.z, b.w};
    unsigned short hb[8], lb[8];
#pragma unroll
    for (int i = 0; i < 8; i++) {
        __nv_bfloat16 h = __float2bfloat16(v[i]);
        float hf = __bfloat162float(h);
        __nv_bfloat16 l = __float2bfloat16(v[i] - hf);
        hb[i] = __bfloat16_as_ushort(h);
        lb[i] = __bfloat16_as_ushort(l);
    }
    uint4 uh, ul;
    uh.x = hb[0] | (uint32_t)hb[1] << 16;  uh.y = hb[2] | (uint32_t)hb[3] << 16;
    uh.z = hb[4] | (uint32_t)hb[5] << 16;  uh.w = hb[6] | (uint32_t)hb[7] << 16;
    ul.x = lb[0] | (uint32_t)lb[1] << 16;  ul.y = lb[2] | (uint32_t)lb[3] << 16;
    ul.z = lb[4] | (uint32_t)lb[5] << 16;  ul.w = lb[6] | (uint32_t)lb[7] << 16;
    *reinterpret_cast<uint4*>(g_Wh + gt * 8) = uh;
    *reinterpret_cast<uint4*>(g_Wl + gt * 8) = ul;
}

// ============================================================================
// Pass 1b: x -> Xh/Xl bf16 in [b][phase][px][c] (K-major)
// ============================================================================
__global__ __launch_bounds__(256)
void convert_x_kernel(const float* __restrict__ x) {
    __shared__ float sin[64][68];
    int bid = blockIdx.x;                 // 16 * 64 * 8 = 8192
    int cc = bid & 7;
    int h  = (bid >> 3) & 63;
    int b  = bid >> 9;
    int c0 = cc * 64;
    int t  = threadIdx.x;

    const float* src = x + (((size_t)b * CIN + c0) * 64 + h) * 64;
    {
        int c  = t >> 2;
        int f0 = t & 3;
#pragma unroll
        for (int j = 0; j < 4; j++) {
            float4 v = *reinterpret_cast<const float4*>(src + (size_t)c * 4096 + (f0 + 4 * j) * 4);
            *reinterpret_cast<float4*>(&sin[c][(f0 + 4 * j) * 4]) = v;
        }
    }
    __syncthreads();

    int p   = t >> 2;
    int q   = p >> 4;
    int w4  = p & 15;
    int cc4 = t & 3;
    int r   = h & 3;
    int h4  = h >> 2;

    unsigned short hb[16], lb[16];
#pragma unroll
    for (int i = 0; i < 16; i++) {
        float v = sin[cc4 * 16 + i][q + 4 * w4];
        __nv_bfloat16 hh = __float2bfloat16(v);
        float hf = __bfloat162float(hh);
        __nv_bfloat16 ll = __float2bfloat16(v - hf);
        hb[i] = __bfloat16_as_ushort(hh);
        lb[i] = __bfloat16_as_ushort(ll);
    }

    int phase = r * 4 + q;
    int px    = h4 * 16 + w4;
    size_t off = (((size_t)(b * 16 + phase) * NPX) + px) * CIN + c0 + cc4 * 16;

    uint4 u0, u1;
    u0.x = hb[0] | (uint32_t)hb[1] << 16;   u0.y = hb[2]  | (uint32_t)hb[3] << 16;
    u0.z = hb[4] | (uint32_t)hb[5] << 16;   u0.w = hb[6]  | (uint32_t)hb[7] << 16;
    u1.x = hb[8] | (uint32_t)hb[9] << 16;   u1.y = hb[10] | (uint32_t)hb[11] << 16;
    u1.z = hb[12]| (uint32_t)hb[13] << 16;  u1.w = hb[14] | (uint32_t)hb[15] << 16;
    *reinterpret_cast<uint4*>(g_Xh + off)     = u0;
    *reinterpret_cast<uint4*>(g_Xh + off + 8) = u1;
    u0.x = lb[0] | (uint32_t)lb[1] << 16;   u0.y = lb[2]  | (uint32_t)lb[3] << 16;
    u0.z = lb[4] | (uint32_t)lb[5] << 16;   u0.w = lb[6]  | (uint32_t)lb[7] << 16;
    u1.x = lb[8] | (uint32_t)lb[9] << 16;   u1.y = lb[10] | (uint32_t)lb[11] << 16;
    u1.z = lb[12]| (uint32_t)lb[13] << 16;  u1.w = lb[14] | (uint32_t)lb[15] << 16;
    *reinterpret_cast<uint4*>(g_Xl + off)     = u0;
    *reinterpret_cast<uint4*>(g_Xl + off + 8) = u1;
}

// ============================================================================
// Pass 2: GEMM, CTA = 256o x 128px, 512 threads, KC=32, 4-stage pipeline.
//   16 warps: mw = wid&3 (64 o-rows), nw = wid>>2 (32 px)
//   stage (48KB): Wh 16K | Wl 16K | Xh 8K | Xl 8K  (64B rows, SW64)
// ============================================================================
#define STAGE_BYTES 49152
#define T_WH 0
#define T_WL 16384
#define T_XH 32768
#define T_XL 40960

__global__ __launch_bounds__(512, 1)
void gwlp_mma_kernel() {
    extern __shared__ __align__(1024) char sm[];
    const uint32_t smb = smem_to_u32(sm);

    const int t   = threadIdx.x;
    const int wid = t >> 5;
    const int lid = t & 31;
    const int mw  = wid & 3;    // o sub-tile (64 rows)
    const int nw  = wid >> 2;   // px sub-tile (32 rows)

    // ptile fastest: bid-adjacent CTA pairs share the identical W tile.
    const int bid   = blockIdx.x;   // 1024
    const int ptile = bid & 1;
    const int otile = (bid >> 1) & 1;
    const int phase = (bid >> 2) & 15;
    const int b     = bid >> 6;
    const int o0    = otile * 256;
    const int px0   = ptile * 128;

    const unsigned short* whp = g_Wh + ((size_t)phase * COUT + o0) * CIN;
    const unsigned short* wlp = g_Wl + ((size_t)phase * COUT + o0) * CIN;
    const unsigned short* xhp = g_Xh + ((size_t)(b * 16 + phase) * NPX + px0) * CIN;
    const unsigned short* xlp = g_Xl + ((size_t)(b * 16 + phase) * NPX + px0) * CIN;

    // ---- stage loader: 6 x 16B cp.async per thread ----
    // W: 1024 granules (256 rows x 4), X: 512 granules (128 rows x 4)
    auto load_stage = [&](int s, int buf) {
        const uint32_t sb = smb + (uint32_t)buf * STAGE_BYTES;
        const int ce = s * KC;
#pragma unroll
        for (int i = 0; i < 2; i++) {
            int gi  = t + i * 512;
            int row = gi >> 2, g = gi & 3;
            uint32_t d = sb + SWZ64(row * 64 + g * 16);
            size_t so = (size_t)row * CIN + ce + g * 8;
            cp_async16(d + T_WH, whp + so);
            cp_async16(d + T_WL, wlp + so);
        }
        {
            int row = t >> 2, g = t & 3;
            uint32_t d = sb + SWZ64(row * 64 + g * 16);
            size_t so = (size_t)row * CIN + ce + g * 8;
            cp_async16(d + T_XH, xhp + so);
            cp_async16(d + T_XL, xlp + so);
        }
        CP_COMMIT();
    };

    // ---- per-lane ldmatrix address components (SW64: key = ((r>>1)&3)<<4) ----
    const int lr = lid & 15;
    const int cb = lid >> 4;
    uint32_t a_off[4], a_key[4];
#pragma unroll
    for (int mt = 0; mt < 4; mt++) {
        int row = mw * 64 + mt * 16 + lr;
        a_off[mt] = (uint32_t)row * 64;
        a_key[mt] = (uint32_t)((row >> 1) & 3) << 4;
    }
    uint32_t b_off[2], b_key[2];
#pragma unroll
    for (int j = 0; j < 2; j++) {
        int row = nw * 32 + j * 16 + lr;
        b_off[j] = (uint32_t)row * 64;
        b_key[j] = (uint32_t)((row >> 1) & 3) << 4;
    }

    float acc[4][4][4];
#pragma unroll
    for (int mt = 0; mt < 4; mt++)
#pragma unroll
        for (int nt = 0; nt < 4; nt++)
#pragma unroll
            for (int e = 0; e < 4; e++)
                acc[mt][nt][e] = 0.0f;

    // ---- 4-stage pipeline, single sync per stage ----
    load_stage(0, 0);
    load_stage(1, 1);
    load_stage(2, 2);

#pragma unroll 1
    for (int ck = 0; ck < NSTAGE; ck++) {
        if (ck < NSTAGE - 2)       { CP_WAIT(2); }
        else if (ck == NSTAGE - 2) { CP_WAIT(1); }
        else                       { CP_WAIT(0); }
        __syncthreads();
        // buffer (ck+3)%4 == (ck-1)%4: computed last iter, safe after sync.
        {
            int nb = ck + 3;
            if (nb < NSTAGE) load_stage(nb, nb & 3);
        }

        const uint32_t sb = smb + (uint32_t)(ck & 3) * STAGE_BYTES;
#pragma unroll
        for (int ks = 0; ks < 2; ks++) {
            const uint32_t col = (uint32_t)(ks * 32 + cb * 16);
            uint32_t bh[2][4], bl[2][4];
#pragma unroll
            for (int j = 0; j < 2; j++) {
                uint32_t bx = b_off[j] + (col ^ b_key[j]);
                ldmx4(bh[j], sb + T_XH + bx);
                ldmx4(bl[j], sb + T_XL + bx);
            }
#pragma unroll
            for (int mt = 0; mt < 4; mt++) {
                uint32_t ah[4], al[4];
                uint32_t ax = a_off[mt] + (col ^ a_key[mt]);
                ldmx4(ah, sb + T_WH + ax);
                ldmx4(al, sb + T_WL + ax);
#pragma unroll
                for (int j = 0; j < 2; j++) {
                    mma16816(acc[mt][2 * j], ah, bh[j][0], bh[j][2]);
                    mma16816(acc[mt][2 * j], ah, bl[j][0], bl[j][2]);
                    mma16816(acc[mt][2 * j], al, bh[j][0], bh[j][2]);
                    mma16816(acc[mt][2 * j + 1], ah, bh[j][1], bh[j][3]);
                    mma16816(acc[mt][2 * j + 1], ah, bl[j][1], bl[j][3]);
                    mma16816(acc[mt][2 * j + 1], al, bh[j][1], bh[j][3]);
                }
            }
        }
    }

    // ---- epilogue: coalesced float2 stores to px-major scratch ----
    const int g  = lid >> 2;
    const int tq = lid & 3;
    float* tb = g_tmp + ((size_t)(b * 16 + phase) * COUT + o0) * NPX + px0;
#pragma unroll
    for (int mt = 0; mt < 4; mt++) {
#pragma unroll
        for (int nt = 0; nt < 4; nt++) {
            int o  = mw * 64 + mt * 16 + g;
            int px = nw * 32 + nt * 8 + tq * 2;
            float2 v0 = make_float2(acc[mt][nt][0], acc[mt][nt][1]);
            float2 v1 = make_float2(acc[mt][nt][2], acc[mt][nt][3]);
            *reinterpret_cast<float2*>(tb + (size_t)o * NPX + px)       = v0;
            *reinterpret_cast<float2*>(tb + (size_t)(o + 8) * NPX + px) = v1;
        }
    }
}

// ============================================================================
// Pass 3: unshuffle g_tmp[b][phase][o][px] -> out[b][o][h][w]
// ============================================================================
__global__ __launch_bounds__(256)
void unshuffle_kernel(float* __restrict__ out) {
    __shared__ float s[4096];
    const int t  = threadIdx.x;
    const int o  = blockIdx.x & 511;
    const int b  = blockIdx.x >> 9;

    const float* src = g_tmp + (size_t)b * 16 * COUT * NPX + (size_t)o * NPX;
#pragma unroll
    for (int i = 0; i < 4; i++) {
        int gi = t + i * 256;
        int ph = gi >> 6, f4 = gi & 63;
        float4 v = *reinterpret_cast<const float4*>(src + (size_t)ph * COUT * NPX + f4 * 4);
        *reinterpret_cast<float4*>(&s[ph * 256 + f4 * 4]) = v;
    }
    __syncthreads();

    const int h  = t >> 2;
    const int wb = (t & 3) * 16;
    const int r  = h & 3;
    const int h4 = h >> 2;
    float* dst = out + ((size_t)(b * COUT + o) * 64 + h) * 64 + wb;
#pragma unroll
    for (int k4 = 0; k4 < 4; k4++) {
        int w4 = (wb >> 2) + k4;
        float4 v;
        v.x = s[(r * 4 + 0) * 256 + h4 * 16 + w4];
        v.y = s[(r * 4 + 1) * 256 + h4 * 16 + w4];
        v.z = s[(r * 4 + 2) * 256 + h4 * 16 + w4];
        v.w = s[(r * 4 + 3) * 256 + h4 * 16 + w4];
        *reinterpret_cast<float4*>(dst + k4 * 4) = v;
    }
}

// ============================================================================
extern "C" void kernel_launch(void* const* d_in, const int* in_sizes, int n_in,
                              void* d_out, int out_size)
{
    const float* x  = (const float*)d_in[0];   // [16, 512, 64, 64]
    const float* Wg = (const float*)d_in[1];   // [16, 512, 512]
    float* out = (float*)d_out;                // [16, 512, 64, 64]

    cudaFuncSetAttribute(gwlp_mma_kernel,
                         cudaFuncAttributeMaxDynamicSharedMemorySize, 4 * STAGE_BYTES);

    convert_w_kernel<<<2048, 256>>>(Wg);
    convert_x_kernel<<<8192, 256>>>(x);
    gwlp_mma_kernel<<<1024, 512, 4 * STAGE_BYTES>>>();
    unshuffle_kernel<<<8192, 256>>>(out);
}

// round 6
// speedup vs baseline: 1.0501x; 1.0501x over previous
#include <cuda_runtime.h>
#include <cuda_bf16.h>
#include <cstdint>

// ============================================================================
// GroupWiseLinearProjector via mma.sync bf16x3-split GEMM (compute_103-safe)
//   out[b,o,h,w] = sum_c x[b,c,h,w] * Wg[p(h,w),o,c],  p=(h%4)*4+(w%4)
// Per (b,phase): D[512 o, 256 px] = W[512,512] * X[256 px, 512]^T
// fp32 = bf16_hi + bf16_lo;  D = Wh*Xh + Wh*Xl + Wl*Xh  (fp32 accum)
// R6: 64x64 warp tiles (85 B smem / MMA, below 128 B/cyc crossbar),
//     CTA 128o x 256px, 8 warps, KC=64/SW128, 2-stage 192KB pipeline.
//     unshuffle: 2 o-planes per block for MLP.
// ============================================================================

#define B_   16
#define CIN  512
#define COUT 512
#define NPX  256
#define KC   64          // K chunk (64 bf16 = 128B row, SW128 swizzle)
#define NSTAGE 8         // 512 / 64

// ---------------- scratch (device globals; no allocation) ----------------
__device__ __align__(256) unsigned short g_Xh[B_ * 16 * NPX * CIN];   // 64MB
__device__ __align__(256) unsigned short g_Xl[B_ * 16 * NPX * CIN];   // 64MB
__device__ __align__(256) unsigned short g_Wh[16 * COUT * CIN];       // 8MB
__device__ __align__(256) unsigned short g_Wl[16 * COUT * CIN];       // 8MB
__device__ __align__(256) float g_tmp[B_ * 16 * COUT * NPX];          // 134MB

// ---------------- helpers ----------------
__device__ __forceinline__ uint32_t smem_to_u32(const void* p) {
    uint32_t a;
    asm("{ .reg .u64 t; cvta.to.shared.u64 t, %1; cvt.u32.u64 %0, t; }"
        : "=r"(a) : "l"(p));
    return a;
}
__device__ __forceinline__ void cp_async16(uint32_t dst, const void* src) {
    asm volatile("cp.async.cg.shared.global [%0], [%1], 16;"
                 :: "r"(dst), "l"(src) : "memory");
}
#define CP_COMMIT() asm volatile("cp.async.commit_group;" ::: "memory")
#define CP_WAIT(n)  asm volatile("cp.async.wait_group %0;" :: "n"(n) : "memory")

__device__ __forceinline__ void ldmx4(uint32_t* r, uint32_t addr) {
    asm volatile("ldmatrix.sync.aligned.m8n8.x4.shared.b16 {%0,%1,%2,%3}, [%4];"
                 : "=r"(r[0]), "=r"(r[1]), "=r"(r[2]), "=r"(r[3]) : "r"(addr));
}
__device__ __forceinline__ void mma16816(float* d, const uint32_t* a,
                                         uint32_t b0, uint32_t b1) {
    asm volatile(
        "mma.sync.aligned.m16n8k16.row.col.f32.bf16.bf16.f32 "
        "{%0,%1,%2,%3}, {%4,%5,%6,%7}, {%8,%9}, {%0,%1,%2,%3};"
        : "+f"(d[0]), "+f"(d[1]), "+f"(d[2]), "+f"(d[3])
        : "r"(a[0]), "r"(a[1]), "r"(a[2]), "r"(a[3]), "r"(b0), "r"(b1));
}
#define SWZ(off) ((uint32_t)(off) ^ ((((uint32_t)(off)) >> 3) & 0x70))

// ============================================================================
// Pass 1a: W -> Wh/Wl bf16 (same layout [ph][o][c])
// ============================================================================
__global__ __launch_bounds__(256)
void convert_w_kernel(const float* __restrict__ Wg) {
    size_t gt = (size_t)blockIdx.x * 256 + threadIdx.x;
    const float4* src = reinterpret_cast<const float4*>(Wg) + gt * 2;
    float4 a = src[0], b = src[1];
    float v[8] = {a.x, a.y, a.z, a.w, b.x, b.y, b.z, b.w};
    unsigned short hb[8], lb[8];
#pragma unroll
    for (int i = 0; i < 8; i++) {
        __nv_bfloat16 h = __float2bfloat16(v[i]);
        float hf = __bfloat162float(h);
        __nv_bfloat16 l = __float2bfloat16(v[i] - hf);
        hb[i] = __bfloat16_as_ushort(h);
        lb[i] = __bfloat16_as_ushort(l);
    }
    uint4 uh, ul;
    uh.x = hb[0] | (uint32_t)hb[1] << 16;  uh.y = hb[2] | (uint32_t)hb[3] << 16;
    uh.z = hb[4] | (uint32_t)hb[5] << 16;  uh.w = hb[6] | (uint32_t)hb[7] << 16;
    ul.x = lb[0] | (uint32_t)lb[1] << 16;  ul.y = lb[2] | (uint32_t)lb[3] << 16;
    ul.z = lb[4] | (uint32_t)lb[5] << 16;  ul.w = lb[6] | (uint32_t)lb[7] << 16;
    *reinterpret_cast<uint4*>(g_Wh + gt * 8) = uh;
    *reinterpret_cast<uint4*>(g_Wl + gt * 8) = ul;
}

// ============================================================================
// Pass 1b: x -> Xh/Xl bf16 in [b][phase][px][c] (K-major)
// ============================================================================
__global__ __launch_bounds__(256)
void convert_x_kernel(const float* __restrict__ x) {
    __shared__ float sin[64][68];
    int bid = blockIdx.x;                 // 16 * 64 * 8 = 8192
    int cc = bid & 7;
    int h  = (bid >> 3) & 63;
    int b  = bid >> 9;
    int c0 = cc * 64;
    int t  = threadIdx.x;

    const float* src = x + (((size_t)b * CIN + c0) * 64 + h) * 64;
    {
        int c  = t >> 2;
        int f0 = t & 3;
#pragma unroll
        for (int j = 0; j < 4; j++) {
            float4 v = *reinterpret_cast<const float4*>(src + (size_t)c * 4096 + (f0 + 4 * j) * 4);
            *reinterpret_cast<float4*>(&sin[c][(f0 + 4 * j) * 4]) = v;
        }
    }
    __syncthreads();

    int p   = t >> 2;
    int q   = p >> 4;
    int w4  = p & 15;
    int cc4 = t & 3;
    int r   = h & 3;
    int h4  = h >> 2;

    unsigned short hb[16], lb[16];
#pragma unroll
    for (int i = 0; i < 16; i++) {
        float v = sin[cc4 * 16 + i][q + 4 * w4];
        __nv_bfloat16 hh = __float2bfloat16(v);
        float hf = __bfloat162float(hh);
        __nv_bfloat16 ll = __float2bfloat16(v - hf);
        hb[i] = __bfloat16_as_ushort(hh);
        lb[i] = __bfloat16_as_ushort(ll);
    }

    int phase = r * 4 + q;
    int px    = h4 * 16 + w4;
    size_t off = (((size_t)(b * 16 + phase) * NPX) + px) * CIN + c0 + cc4 * 16;

    uint4 u0, u1;
    u0.x = hb[0] | (uint32_t)hb[1] << 16;   u0.y = hb[2]  | (uint32_t)hb[3] << 16;
    u0.z = hb[4] | (uint32_t)hb[5] << 16;   u0.w = hb[6]  | (uint32_t)hb[7] << 16;
    u1.x = hb[8] | (uint32_t)hb[9] << 16;   u1.y = hb[10] | (uint32_t)hb[11] << 16;
    u1.z = hb[12]| (uint32_t)hb[13] << 16;  u1.w = hb[14] | (uint32_t)hb[15] << 16;
    *reinterpret_cast<uint4*>(g_Xh + off)     = u0;
    *reinterpret_cast<uint4*>(g_Xh + off + 8) = u1;
    u0.x = lb[0] | (uint32_t)lb[1] << 16;   u0.y = lb[2]  | (uint32_t)lb[3] << 16;
    u0.z = lb[4] | (uint32_t)lb[5] << 16;   u0.w = lb[6]  | (uint32_t)lb[7] << 16;
    u1.x = lb[8] | (uint32_t)lb[9] << 16;   u1.y = lb[10] | (uint32_t)lb[11] << 16;
    u1.z = lb[12]| (uint32_t)lb[13] << 16;  u1.w = lb[14] | (uint32_t)lb[15] << 16;
    *reinterpret_cast<uint4*>(g_Xl + off)     = u0;
    *reinterpret_cast<uint4*>(g_Xl + off + 8) = u1;
}

// ============================================================================
// Pass 2: GEMM, CTA = 128o x 256px, 256 threads, 8 warps of 64x64.
//   mw = wid&1 (64 o-rows), nw = wid>>1 (64 px)
//   stage (96KB): Wh 16K | Wl 16K | Xh 32K | Xl 32K  (128B rows, SW128); x2
// ============================================================================
#define STAGE_BYTES 98304
#define T_WH 0
#define T_WL 16384
#define T_XH 32768
#define T_XL 65536

__global__ __launch_bounds__(256, 1)
void gwlp_mma_kernel() {
    extern __shared__ __align__(1024) char sm[];
    const uint32_t smb = smem_to_u32(sm);

    const int t   = threadIdx.x;
    const int wid = t >> 5;
    const int lid = t & 31;
    const int mw  = wid & 1;    // o sub-tile (64 rows)
    const int nw  = wid >> 1;   // px sub-tile (64 rows)

    // otile fastest: 4 adjacent CTAs share the same X tile via L2.
    const int bid   = blockIdx.x;   // 1024
    const int otile = bid & 3;
    const int phase = (bid >> 2) & 15;
    const int b     = bid >> 6;
    const int o0    = otile * 128;

    const unsigned short* whp = g_Wh + ((size_t)phase * COUT + o0) * CIN;
    const unsigned short* wlp = g_Wl + ((size_t)phase * COUT + o0) * CIN;
    const unsigned short* xhp = g_Xh + (size_t)(b * 16 + phase) * NPX * CIN;
    const unsigned short* xlp = g_Xl + (size_t)(b * 16 + phase) * NPX * CIN;

    // ---- stage loader: 24 x 16B cp.async per thread ----
    auto load_stage = [&](int s, int buf) {
        const uint32_t sb = smb + (uint32_t)buf * STAGE_BYTES;
        const int ce = s * KC;
#pragma unroll
        for (int i = 0; i < 4; i++) {      // W: 1024 granules
            int gi  = t + i * 256;
            int row = gi >> 3, g = gi & 7;
            uint32_t d = sb + SWZ(row * 128 + g * 16);
            size_t so = (size_t)row * CIN + ce + g * 8;
            cp_async16(d + T_WH, whp + so);
            cp_async16(d + T_WL, wlp + so);
        }
#pragma unroll
        for (int i = 0; i < 8; i++) {      // X: 2048 granules
            int gi  = t + i * 256;
            int row = gi >> 3, g = gi & 7;
            uint32_t d = sb + SWZ(row * 128 + g * 16);
            size_t so = (size_t)row * CIN + ce + g * 8;
            cp_async16(d + T_XH, xhp + so);
            cp_async16(d + T_XL, xlp + so);
        }
        CP_COMMIT();
    };

    // ---- per-lane ldmatrix address components ----
    const int lr = lid & 15;
    const int cb = lid >> 4;
    uint32_t a_off[4], a_key[4];
#pragma unroll
    for (int mt = 0; mt < 4; mt++) {
        int row = mw * 64 + mt * 16 + lr;
        a_off[mt] = (uint32_t)row * 128;
        a_key[mt] = (uint32_t)(row & 7) << 4;
    }
    uint32_t b_off[4], b_key[4];
#pragma unroll
    for (int j = 0; j < 4; j++) {
        int row = nw * 64 + j * 16 + lr;
        b_off[j] = (uint32_t)row * 128;
        b_key[j] = (uint32_t)(row & 7) << 4;
    }

    float acc[4][8][4];
#pragma unroll
    for (int mt = 0; mt < 4; mt++)
#pragma unroll
        for (int nt = 0; nt < 8; nt++)
#pragma unroll
            for (int e = 0; e < 4; e++)
                acc[mt][nt][e] = 0.0f;

    // ---- 2-stage pipeline ----
    load_stage(0, 0);
    load_stage(1, 1);

#pragma unroll 1
    for (int ck = 0; ck < NSTAGE; ck++) {
        if (ck == NSTAGE - 1) { CP_WAIT(0); } else { CP_WAIT(1); }
        __syncthreads();

        const uint32_t sb = smb + (uint32_t)(ck & 1) * STAGE_BYTES;
#pragma unroll
        for (int ks = 0; ks < 4; ks++) {
            const uint32_t col = (uint32_t)(ks * 32 + cb * 16);
            uint32_t bh[4][4], bl[4][4];
#pragma unroll
            for (int j = 0; j < 4; j++) {
                uint32_t bx = b_off[j] + (col ^ b_key[j]);
                ldmx4(bh[j], sb + T_XH + bx);
                ldmx4(bl[j], sb + T_XL + bx);
            }
#pragma unroll
            for (int mt = 0; mt < 4; mt++) {
                uint32_t ah[4], al[4];
                uint32_t ax = a_off[mt] + (col ^ a_key[mt]);
                ldmx4(ah, sb + T_WH + ax);
                ldmx4(al, sb + T_WL + ax);
#pragma unroll
                for (int j = 0; j < 4; j++) {
                    mma16816(acc[mt][2 * j], ah, bh[j][0], bh[j][2]);
                    mma16816(acc[mt][2 * j], ah, bl[j][0], bl[j][2]);
                    mma16816(acc[mt][2 * j], al, bh[j][0], bh[j][2]);
                    mma16816(acc[mt][2 * j + 1], ah, bh[j][1], bh[j][3]);
                    mma16816(acc[mt][2 * j + 1], ah, bl[j][1], bl[j][3]);
                    mma16816(acc[mt][2 * j + 1], al, bh[j][1], bh[j][3]);
                }
            }
        }
        __syncthreads();
        if (ck + 2 < NSTAGE) load_stage(ck + 2, ck & 1);
    }

    // ---- epilogue: coalesced float2 stores to px-major scratch ----
    const int g  = lid >> 2;
    const int tq = lid & 3;
    float* tb = g_tmp + ((size_t)(b * 16 + phase) * COUT + o0) * NPX;
#pragma unroll
    for (int mt = 0; mt < 4; mt++) {
#pragma unroll
        for (int nt = 0; nt < 8; nt++) {
            int o  = mw * 64 + mt * 16 + g;
            int px = nw * 64 + nt * 8 + tq * 2;
            float2 v0 = make_float2(acc[mt][nt][0], acc[mt][nt][1]);
            float2 v1 = make_float2(acc[mt][nt][2], acc[mt][nt][3]);
            *reinterpret_cast<float2*>(tb + (size_t)o * NPX + px)       = v0;
            *reinterpret_cast<float2*>(tb + (size_t)(o + 8) * NPX + px) = v1;
        }
    }
}

// ============================================================================
// Pass 3: unshuffle g_tmp[b][phase][o][px] -> out[b][o][h][w]
//   2 o-planes per block (MLP 8 on the strided loads)
// ============================================================================
__global__ __launch_bounds__(256)
void unshuffle_kernel(float* __restrict__ out) {
    __shared__ float s[2][4096];
    const int t  = threadIdx.x;
    const int o0 = (blockIdx.x & 255) * 2;
    const int b  = blockIdx.x >> 8;

    const float* src = g_tmp + (size_t)b * 16 * COUT * NPX;
#pragma unroll
    for (int oo = 0; oo < 2; oo++) {
#pragma unroll
        for (int i = 0; i < 4; i++) {
            int gi = t + i * 256;
            int ph = gi >> 6, f4 = gi & 63;
            float4 v = *reinterpret_cast<const float4*>(
                src + (size_t)ph * COUT * NPX + (size_t)(o0 + oo) * NPX + f4 * 4);
            *reinterpret_cast<float4*>(&s[oo][ph * 256 + f4 * 4]) = v;
        }
    }
    __syncthreads();

    const int h  = t >> 2;
    const int wb = (t & 3) * 16;
    const int r  = h & 3;
    const int h4 = h >> 2;
#pragma unroll
    for (int oo = 0; oo < 2; oo++) {
        float* dst = out + ((size_t)(b * COUT + o0 + oo) * 64 + h) * 64 + wb;
#pragma unroll
        for (int k4 = 0; k4 < 4; k4++) {
            int w4 = (wb >> 2) + k4;
            float4 v;
            v.x = s[oo][(r * 4 + 0) * 256 + h4 * 16 + w4];
            v.y = s[oo][(r * 4 + 1) * 256 + h4 * 16 + w4];
            v.z = s[oo][(r * 4 + 2) * 256 + h4 * 16 + w4];
            v.w = s[oo][(r * 4 + 3) * 256 + h4 * 16 + w4];
            *reinterpret_cast<float4*>(dst + k4 * 4) = v;
        }
    }
}

// ============================================================================
extern "C" void kernel_launch(void* const* d_in, const int* in_sizes, int n_in,
                              void* d_out, int out_size)
{
    const float* x  = (const float*)d_in[0];   // [16, 512, 64, 64]
    const float* Wg = (const float*)d_in[1];   // [16, 512, 512]
    float* out = (float*)d_out;                // [16, 512, 64, 64]

    cudaFuncSetAttribute(gwlp_mma_kernel,
                         cudaFuncAttributeMaxDynamicSharedMemorySize, 2 * STAGE_BYTES);

    convert_w_kernel<<<2048, 256>>>(Wg);
    convert_x_kernel<<<8192, 256>>>(x);
    gwlp_mma_kernel<<<1024, 256, 2 * STAGE_BYTES>>>();
    unshuffle_kernel<<<4096, 256>>>(out);
}

// round 7
// speedup vs baseline: 1.8907x; 1.8005x over previous
#include <cuda_runtime.h>
#include <cuda_fp16.h>
#include <cstdint>

// ============================================================================
// GroupWiseLinearProjector via single-pass fp16 mma.sync GEMM (compute_103)
//   out[b,o,h,w] = sum_c x[b,c,h,w] * Wg[p(h,w),o,c],  p=(h%4)*4+(w%4)
// Per (b,phase): D[512 o, 256 px] = W[512,512] * X[256 px, 512]^T
// fp16 operands, fp32 accumulate. Predicted L2 rel_err ~4e-4 (<1e-3).
// R7: 1 MMA pass (3x fewer MMAs), 4-stage 48KB pipeline,
//     g_tmp[b][o][phase][px] for streaming unshuffle reads.
// ============================================================================

#define B_   16
#define CIN  512
#define COUT 512
#define NPX  256
#define KC   64          // K chunk (64 fp16 = 128B row, SW128 swizzle)
#define NSTAGE 8         // 512 / 64

// ---------------- scratch (device globals; no allocation) ----------------
__device__ __align__(256) unsigned short g_Xh[B_ * 16 * NPX * CIN];   // 64MB
__device__ __align__(256) unsigned short g_Wh[16 * COUT * CIN];       // 8MB
__device__ __align__(256) float g_tmp[B_ * COUT * 16 * NPX];          // 134MB

// ---------------- helpers ----------------
__device__ __forceinline__ uint32_t smem_to_u32(const void* p) {
    uint32_t a;
    asm("{ .reg .u64 t; cvta.to.shared.u64 t, %1; cvt.u32.u64 %0, t; }"
        : "=r"(a) : "l"(p));
    return a;
}
__device__ __forceinline__ void cp_async16(uint32_t dst, const void* src) {
    asm volatile("cp.async.cg.shared.global [%0], [%1], 16;"
                 :: "r"(dst), "l"(src) : "memory");
}
#define CP_COMMIT() asm volatile("cp.async.commit_group;" ::: "memory")
#define CP_WAIT(n)  asm volatile("cp.async.wait_group %0;" :: "n"(n) : "memory")

__device__ __forceinline__ void ldmx4(uint32_t* r, uint32_t addr) {
    asm volatile("ldmatrix.sync.aligned.m8n8.x4.shared.b16 {%0,%1,%2,%3}, [%4];"
                 : "=r"(r[0]), "=r"(r[1]), "=r"(r[2]), "=r"(r[3]) : "r"(addr));
}
__device__ __forceinline__ void mma16816(float* d, const uint32_t* a,
                                         uint32_t b0, uint32_t b1) {
    asm volatile(
        "mma.sync.aligned.m16n8k16.row.col.f32.f16.f16.f32 "
        "{%0,%1,%2,%3}, {%4,%5,%6,%7}, {%8,%9}, {%0,%1,%2,%3};"
        : "+f"(d[0]), "+f"(d[1]), "+f"(d[2]), "+f"(d[3])
        : "r"(a[0]), "r"(a[1]), "r"(a[2]), "r"(a[3]), "r"(b0), "r"(b1));
}
#define SWZ(off) ((uint32_t)(off) ^ ((((uint32_t)(off)) >> 3) & 0x70))

// ============================================================================
// Pass 1a: W -> fp16 (layout [ph][o][c])
// ============================================================================
__global__ __launch_bounds__(256)
void convert_w_kernel(const float* __restrict__ Wg) {
    size_t gt = (size_t)blockIdx.x * 256 + threadIdx.x;
    const float4* src = reinterpret_cast<const float4*>(Wg) + gt * 2;
    float4 a = src[0], b = src[1];
    float v[8] = {a.x, a.y, a.z, a.w, b.x, b.y, b.z, b.w};
    unsigned short hb[8];
#pragma unroll
    for (int i = 0; i < 8; i++)
        hb[i] = __half_as_ushort(__float2half_rn(v[i]));
    uint4 uh;
    uh.x = hb[0] | (uint32_t)hb[1] << 16;  uh.y = hb[2] | (uint32_t)hb[3] << 16;
    uh.z = hb[4] | (uint32_t)hb[5] << 16;  uh.w = hb[6] | (uint32_t)hb[7] << 16;
    *reinterpret_cast<uint4*>(g_Wh + gt * 8) = uh;
}

// ============================================================================
// Pass 1b: x -> fp16 in [b][phase][px][c] (K-major)
// ============================================================================
__global__ __launch_bounds__(256)
void convert_x_kernel(const float* __restrict__ x) {
    __shared__ float sin[64][68];
    int bid = blockIdx.x;                 // 16 * 64 * 8 = 8192
    int cc = bid & 7;
    int h  = (bid >> 3) & 63;
    int b  = bid >> 9;
    int c0 = cc * 64;
    int t  = threadIdx.x;

    const float* src = x + (((size_t)b * CIN + c0) * 64 + h) * 64;
    {
        int c  = t >> 2;
        int f0 = t & 3;
#pragma unroll
        for (int j = 0; j < 4; j++) {
            float4 v = *reinterpret_cast<const float4*>(src + (size_t)c * 4096 + (f0 + 4 * j) * 4);
            *reinterpret_cast<float4*>(&sin[c][(f0 + 4 * j) * 4]) = v;
        }
    }
    __syncthreads();

    int p   = t >> 2;
    int q   = p >> 4;
    int w4  = p & 15;
    int cc4 = t & 3;
    int r   = h & 3;
    int h4  = h >> 2;

    unsigned short hb[16];
#pragma unroll
    for (int i = 0; i < 16; i++)
        hb[i] = __half_as_ushort(__float2half_rn(sin[cc4 * 16 + i][q + 4 * w4]));

    int phase = r * 4 + q;
    int px    = h4 * 16 + w4;
    size_t off = (((size_t)(b * 16 + phase) * NPX) + px) * CIN + c0 + cc4 * 16;

    uint4 u0, u1;
    u0.x = hb[0] | (uint32_t)hb[1] << 16;   u0.y = hb[2]  | (uint32_t)hb[3] << 16;
    u0.z = hb[4] | (uint32_t)hb[5] << 16;   u0.w = hb[6]  | (uint32_t)hb[7] << 16;
    u1.x = hb[8] | (uint32_t)hb[9] << 16;   u1.y = hb[10] | (uint32_t)hb[11] << 16;
    u1.z = hb[12]| (uint32_t)hb[13] << 16;  u1.w = hb[14] | (uint32_t)hb[15] << 16;
    *reinterpret_cast<uint4*>(g_Xh + off)     = u0;
    *reinterpret_cast<uint4*>(g_Xh + off + 8) = u1;
}

// ============================================================================
// Pass 2: GEMM, CTA = 128o x 256px, 256 threads, 8 warps of 64x64.
//   stage (48KB): Wh 16K | Xh 32K  (128B rows, SW128); 4 stages = 192KB
// ============================================================================
#define STAGE_BYTES 49152
#define T_WH 0
#define T_XH 16384

__global__ __launch_bounds__(256, 1)
void gwlp_mma_kernel() {
    extern __shared__ __align__(1024) char sm[];
    const uint32_t smb = smem_to_u32(sm);

    const int t   = threadIdx.x;
    const int wid = t >> 5;
    const int lid = t & 31;
    const int mw  = wid & 1;    // o sub-tile (64 rows)
    const int nw  = wid >> 1;   // px sub-tile (64 rows)

    // otile fastest: 4 adjacent CTAs share the same X tile via L2.
    const int bid   = blockIdx.x;   // 1024
    const int otile = bid & 3;
    const int phase = (bid >> 2) & 15;
    const int b     = bid >> 6;
    const int o0    = otile * 128;

    const unsigned short* whp = g_Wh + ((size_t)phase * COUT + o0) * CIN;
    const unsigned short* xhp = g_Xh + (size_t)(b * 16 + phase) * NPX * CIN;

    // ---- stage loader: 12 x 16B cp.async per thread ----
    auto load_stage = [&](int s, int buf) {
        const uint32_t sb = smb + (uint32_t)buf * STAGE_BYTES;
        const int ce = s * KC;
#pragma unroll
        for (int i = 0; i < 4; i++) {      // W: 1024 granules (128 rows x 8)
            int gi  = t + i * 256;
            int row = gi >> 3, g = gi & 7;
            uint32_t d = sb + SWZ(row * 128 + g * 16);
            cp_async16(d + T_WH, whp + (size_t)row * CIN + ce + g * 8);
        }
#pragma unroll
        for (int i = 0; i < 8; i++) {      // X: 2048 granules (256 rows x 8)
            int gi  = t + i * 256;
            int row = gi >> 3, g = gi & 7;
            uint32_t d = sb + SWZ(row * 128 + g * 16);
            cp_async16(d + T_XH, xhp + (size_t)row * CIN + ce + g * 8);
        }
        CP_COMMIT();
    };

    // ---- per-lane ldmatrix address components ----
    const int lr = lid & 15;
    const int cb = lid >> 4;
    uint32_t a_off[4], a_key[4];
#pragma unroll
    for (int mt = 0; mt < 4; mt++) {
        int row = mw * 64 + mt * 16 + lr;
        a_off[mt] = (uint32_t)row * 128;
        a_key[mt] = (uint32_t)(row & 7) << 4;
    }
    uint32_t b_off[4], b_key[4];
#pragma unroll
    for (int j = 0; j < 4; j++) {
        int row = nw * 64 + j * 16 + lr;
        b_off[j] = (uint32_t)row * 128;
        b_key[j] = (uint32_t)(row & 7) << 4;
    }

    float acc[4][8][4];
#pragma unroll
    for (int mt = 0; mt < 4; mt++)
#pragma unroll
        for (int nt = 0; nt < 8; nt++)
#pragma unroll
            for (int e = 0; e < 4; e++)
                acc[mt][nt][e] = 0.0f;

    // ---- 4-stage pipeline, single sync per stage ----
    load_stage(0, 0);
    load_stage(1, 1);
    load_stage(2, 2);

#pragma unroll 1
    for (int ck = 0; ck < NSTAGE; ck++) {
        if (ck < NSTAGE - 2)       { CP_WAIT(2); }
        else if (ck == NSTAGE - 2) { CP_WAIT(1); }
        else                       { CP_WAIT(0); }
        __syncthreads();
        // buffer (ck+3)%4 == (ck-1)%4: computed last iter, safe after sync.
        {
            int nb = ck + 3;
            if (nb < NSTAGE) load_stage(nb, nb & 3);
        }

        const uint32_t sb = smb + (uint32_t)(ck & 3) * STAGE_BYTES;
#pragma unroll
        for (int ks = 0; ks < 4; ks++) {
            const uint32_t col = (uint32_t)(ks * 32 + cb * 16);
            uint32_t bh[4][4];
#pragma unroll
            for (int j = 0; j < 4; j++)
                ldmx4(bh[j], sb + T_XH + b_off[j] + (col ^ b_key[j]));
#pragma unroll
            for (int mt = 0; mt < 4; mt++) {
                uint32_t ah[4];
                ldmx4(ah, sb + T_WH + a_off[mt] + (col ^ a_key[mt]));
#pragma unroll
                for (int j = 0; j < 4; j++) {
                    mma16816(acc[mt][2 * j],     ah, bh[j][0], bh[j][2]);
                    mma16816(acc[mt][2 * j + 1], ah, bh[j][1], bh[j][3]);
                }
            }
        }
    }

    // ---- epilogue: float2 stores to g_tmp[b][o][phase][px] ----
    const int g  = lid >> 2;
    const int tq = lid & 3;
    float* tb = g_tmp + (((size_t)b * COUT + o0) * 16 + phase) * NPX;
#pragma unroll
    for (int mt = 0; mt < 4; mt++) {
#pragma unroll
        for (int nt = 0; nt < 8; nt++) {
            int o  = mw * 64 + mt * 16 + g;
            int px = nw * 64 + nt * 8 + tq * 2;
            float2 v0 = make_float2(acc[mt][nt][0], acc[mt][nt][1]);
            float2 v1 = make_float2(acc[mt][nt][2], acc[mt][nt][3]);
            *reinterpret_cast<float2*>(tb + (size_t)o * (16 * NPX) + px)       = v0;
            *reinterpret_cast<float2*>(tb + (size_t)(o + 8) * (16 * NPX) + px) = v1;
        }
    }
}

// ============================================================================
// Pass 3: unshuffle g_tmp[b][o][phase][px] -> out[b][o][h][w]
//   block = one (b,o) plane; contiguous 16KB read, swizzled smem (f4 ^ r).
// ============================================================================
__global__ __launch_bounds__(256)
void unshuffle_kernel(float* __restrict__ out) {
    __shared__ float s[4096];
    float4* s4 = reinterpret_cast<float4*>(s);
    const int t  = threadIdx.x;
    const int o  = blockIdx.x & 511;
    const int b  = blockIdx.x >> 9;

    const float4* src = reinterpret_cast<const float4*>(
        g_tmp + ((size_t)b * COUT + o) * (16 * NPX));
#pragma unroll
    for (int i = 0; i < 4; i++) {
        int gi = t + i * 256;            // float4 index 0..1023
        int ph = gi >> 6, f4 = gi & 63;
        s4[ph * 64 + (f4 ^ (ph >> 2))] = src[gi];
    }
    __syncthreads();

    const int h  = t >> 2;
    const int wb = (t & 3) * 16;
    const int r  = h & 3;
    const int h4 = h >> 2;
    float* dst = out + ((size_t)(b * COUT + o) * 64 + h) * 64 + wb;
#pragma unroll
    for (int k4 = 0; k4 < 4; k4++) {
        int w4 = (wb >> 2) + k4;
        int f4 = h4 * 4 + (w4 >> 2);     // w4>>2 == (t&3)
        int fs = (f4 ^ r) * 4 + (w4 & 3);
        float4 v;
        v.x = s[(r * 4 + 0) * 256 + fs];
        v.y = s[(r * 4 + 1) * 256 + fs];
        v.z = s[(r * 4 + 2) * 256 + fs];
        v.w = s[(r * 4 + 3) * 256 + fs];
        *reinterpret_cast<float4*>(dst + k4 * 4) = v;
    }
}

// ============================================================================
extern "C" void kernel_launch(void* const* d_in, const int* in_sizes, int n_in,
                              void* d_out, int out_size)
{
    const float* x  = (const float*)d_in[0];   // [16, 512, 64, 64]
    const float* Wg = (const float*)d_in[1];   // [16, 512, 512]
    float* out = (float*)d_out;                // [16, 512, 64, 64]

    cudaFuncSetAttribute(gwlp_mma_kernel,
                         cudaFuncAttributeMaxDynamicSharedMemorySize, 4 * STAGE_BYTES);

    convert_w_kernel<<<2048, 256>>>(Wg);
    convert_x_kernel<<<8192, 256>>>(x);
    gwlp_mma_kernel<<<1024, 256, 4 * STAGE_BYTES>>>();
    unshuffle_kernel<<<8192, 256>>>(out);
}

// round 8
// speedup vs baseline: 1.8916x; 1.0005x over previous
#include <cuda_runtime.h>
#include <cuda_fp16.h>
#include <cstdint>

// ============================================================================
// GroupWiseLinearProjector via single-pass fp16 mma.sync GEMM (compute_103)
//   out[b,o,h,w] = sum_c x[b,c,h,w] * Wg[p(h,w),o,c],  p=(h%4)*4+(w%4)
// Per (b,phase): D[512 o, 256 px] = W[512,512] * X[256 px, 512]^T
// R8: fp16 accumulators (2x HMMA rate) with fp32 promotion every 128 K,
//     fp16 g_tmp scratch (half the round-trip traffic).
// ============================================================================

#define B_   16
#define CIN  512
#define COUT 512
#define NPX  256
#define KC   64          // K chunk (64 fp16 = 128B row, SW128 swizzle)
#define NSTAGE 8         // 512 / 64

// ---------------- scratch (device globals; no allocation) ----------------
__device__ __align__(256) unsigned short g_Xh[B_ * 16 * NPX * CIN];    // 64MB
__device__ __align__(256) unsigned short g_Wh[16 * COUT * CIN];        // 8MB
__device__ __align__(256) unsigned short g_T16[B_ * COUT * 16 * NPX];  // 67MB

// ---------------- helpers ----------------
__device__ __forceinline__ uint32_t smem_to_u32(const void* p) {
    uint32_t a;
    asm("{ .reg .u64 t; cvta.to.shared.u64 t, %1; cvt.u32.u64 %0, t; }"
        : "=r"(a) : "l"(p));
    return a;
}
__device__ __forceinline__ void cp_async16(uint32_t dst, const void* src) {
    asm volatile("cp.async.cg.shared.global [%0], [%1], 16;"
                 :: "r"(dst), "l"(src) : "memory");
}
#define CP_COMMIT() asm volatile("cp.async.commit_group;" ::: "memory")
#define CP_WAIT(n)  asm volatile("cp.async.wait_group %0;" :: "n"(n) : "memory")

__device__ __forceinline__ void ldmx4(uint32_t* r, uint32_t addr) {
    asm volatile("ldmatrix.sync.aligned.m8n8.x4.shared.b16 {%0,%1,%2,%3}, [%4];"
                 : "=r"(r[0]), "=r"(r[1]), "=r"(r[2]), "=r"(r[3]) : "r"(addr));
}
// fp16-accumulator HMMA: d,c are 2x f16x2 regs
__device__ __forceinline__ void mma16816_h(uint32_t* d, const uint32_t* a,
                                           uint32_t b0, uint32_t b1) {
    asm volatile(
        "mma.sync.aligned.m16n8k16.row.col.f16.f16.f16.f16 "
        "{%0,%1}, {%2,%3,%4,%5}, {%6,%7}, {%0,%1};"
        : "+r"(d[0]), "+r"(d[1])
        : "r"(a[0]), "r"(a[1]), "r"(a[2]), "r"(a[3]), "r"(b0), "r"(b1));
}
#define SWZ(off) ((uint32_t)(off) ^ ((((uint32_t)(off)) >> 3) & 0x70))

// ============================================================================
// Pass 1a: W -> fp16 (layout [ph][o][c])
// ============================================================================
__global__ __launch_bounds__(256)
void convert_w_kernel(const float* __restrict__ Wg) {
    size_t gt = (size_t)blockIdx.x * 256 + threadIdx.x;
    const float4* src = reinterpret_cast<const float4*>(Wg) + gt * 2;
    float4 a = src[0], b = src[1];
    float v[8] = {a.x, a.y, a.z, a.w, b.x, b.y, b.z, b.w};
    unsigned short hb[8];
#pragma unroll
    for (int i = 0; i < 8; i++)
        hb[i] = __half_as_ushort(__float2half_rn(v[i]));
    uint4 uh;
    uh.x = hb[0] | (uint32_t)hb[1] << 16;  uh.y = hb[2] | (uint32_t)hb[3] << 16;
    uh.z = hb[4] | (uint32_t)hb[5] << 16;  uh.w = hb[6] | (uint32_t)hb[7] << 16;
    *reinterpret_cast<uint4*>(g_Wh + gt * 8) = uh;
}

// ============================================================================
// Pass 1b: x -> fp16 in [b][phase][px][c] (K-major)
// ============================================================================
__global__ __launch_bounds__(256)
void convert_x_kernel(const float* __restrict__ x) {
    __shared__ float sin[64][68];
    int bid = blockIdx.x;                 // 16 * 64 * 8 = 8192
    int cc = bid & 7;
    int h  = (bid >> 3) & 63;
    int b  = bid >> 9;
    int c0 = cc * 64;
    int t  = threadIdx.x;

    const float* src = x + (((size_t)b * CIN + c0) * 64 + h) * 64;
    {
        int c  = t >> 2;
        int f0 = t & 3;
#pragma unroll
        for (int j = 0; j < 4; j++) {
            float4 v = *reinterpret_cast<const float4*>(src + (size_t)c * 4096 + (f0 + 4 * j) * 4);
            *reinterpret_cast<float4*>(&sin[c][(f0 + 4 * j) * 4]) = v;
        }
    }
    __syncthreads();

    int p   = t >> 2;
    int q   = p >> 4;
    int w4  = p & 15;
    int cc4 = t & 3;
    int r   = h & 3;
    int h4  = h >> 2;

    unsigned short hb[16];
#pragma unroll
    for (int i = 0; i < 16; i++)
        hb[i] = __half_as_ushort(__float2half_rn(sin[cc4 * 16 + i][q + 4 * w4]));

    int phase = r * 4 + q;
    int px    = h4 * 16 + w4;
    size_t off = (((size_t)(b * 16 + phase) * NPX) + px) * CIN + c0 + cc4 * 16;

    uint4 u0, u1;
    u0.x = hb[0] | (uint32_t)hb[1] << 16;   u0.y = hb[2]  | (uint32_t)hb[3] << 16;
    u0.z = hb[4] | (uint32_t)hb[5] << 16;   u0.w = hb[6]  | (uint32_t)hb[7] << 16;
    u1.x = hb[8] | (uint32_t)hb[9] << 16;   u1.y = hb[10] | (uint32_t)hb[11] << 16;
    u1.z = hb[12]| (uint32_t)hb[13] << 16;  u1.w = hb[14] | (uint32_t)hb[15] << 16;
    *reinterpret_cast<uint4*>(g_Xh + off)     = u0;
    *reinterpret_cast<uint4*>(g_Xh + off + 8) = u1;
}

// ============================================================================
// Pass 2: GEMM, CTA = 128o x 256px, 256 threads, 8 warps of 64x64.
//   fp16 accumulators, promoted to fp32 masters every 2 chunks (128 K).
//   stage (48KB): Wh 16K | Xh 32K  (128B rows, SW128); 4 stages = 192KB
// ============================================================================
#define STAGE_BYTES 49152
#define T_WH 0
#define T_XH 16384

__global__ __launch_bounds__(256, 1)
void gwlp_mma_kernel() {
    extern __shared__ __align__(1024) char sm[];
    const uint32_t smb = smem_to_u32(sm);

    const int t   = threadIdx.x;
    const int wid = t >> 5;
    const int lid = t & 31;
    const int mw  = wid & 1;    // o sub-tile (64 rows)
    const int nw  = wid >> 1;   // px sub-tile (64 rows)

    const int bid   = blockIdx.x;   // 1024; otile fastest -> X shared via L2
    const int otile = bid & 3;
    const int phase = (bid >> 2) & 15;
    const int b     = bid >> 6;
    const int o0    = otile * 128;

    const unsigned short* whp = g_Wh + ((size_t)phase * COUT + o0) * CIN;
    const unsigned short* xhp = g_Xh + (size_t)(b * 16 + phase) * NPX * CIN;

    auto load_stage = [&](int s, int buf) {
        const uint32_t sb = smb + (uint32_t)buf * STAGE_BYTES;
        const int ce = s * KC;
#pragma unroll
        for (int i = 0; i < 4; i++) {      // W: 1024 granules
            int gi  = t + i * 256;
            int row = gi >> 3, g = gi & 7;
            uint32_t d = sb + SWZ(row * 128 + g * 16);
            cp_async16(d + T_WH, whp + (size_t)row * CIN + ce + g * 8);
        }
#pragma unroll
        for (int i = 0; i < 8; i++) {      // X: 2048 granules
            int gi  = t + i * 256;
            int row = gi >> 3, g = gi & 7;
            uint32_t d = sb + SWZ(row * 128 + g * 16);
            cp_async16(d + T_XH, xhp + (size_t)row * CIN + ce + g * 8);
        }
        CP_COMMIT();
    };

    const int lr = lid & 15;
    const int cb = lid >> 4;
    uint32_t a_off[4], a_key[4];
#pragma unroll
    for (int mt = 0; mt < 4; mt++) {
        int row = mw * 64 + mt * 16 + lr;
        a_off[mt] = (uint32_t)row * 128;
        a_key[mt] = (uint32_t)(row & 7) << 4;
    }
    uint32_t b_off[4], b_key[4];
#pragma unroll
    for (int j = 0; j < 4; j++) {
        int row = nw * 64 + j * 16 + lr;
        b_off[j] = (uint32_t)row * 128;
        b_key[j] = (uint32_t)(row & 7) << 4;
    }

    float acc[4][8][4];          // fp32 masters
    uint32_t acc16[4][8][2];     // fp16 working accumulators (f16x2 pairs)
#pragma unroll
    for (int mt = 0; mt < 4; mt++)
#pragma unroll
        for (int nt = 0; nt < 8; nt++) {
#pragma unroll
            for (int e = 0; e < 4; e++) acc[mt][nt][e] = 0.0f;
            acc16[mt][nt][0] = 0u; acc16[mt][nt][1] = 0u;
        }

    load_stage(0, 0);
    load_stage(1, 1);
    load_stage(2, 2);

#pragma unroll 1
    for (int ck = 0; ck < NSTAGE; ck++) {
        if (ck < NSTAGE - 2)       { CP_WAIT(2); }
        else if (ck == NSTAGE - 2) { CP_WAIT(1); }
        else                       { CP_WAIT(0); }
        __syncthreads();
        {
            int nb = ck + 3;
            if (nb < NSTAGE) load_stage(nb, nb & 3);
        }

        const uint32_t sb = smb + (uint32_t)(ck & 3) * STAGE_BYTES;
#pragma unroll
        for (int ks = 0; ks < 4; ks++) {
            const uint32_t col = (uint32_t)(ks * 32 + cb * 16);
            uint32_t bh[4][4];
#pragma unroll
            for (int j = 0; j < 4; j++)
                ldmx4(bh[j], sb + T_XH + b_off[j] + (col ^ b_key[j]));
#pragma unroll
            for (int mt = 0; mt < 4; mt++) {
                uint32_t ah[4];
                ldmx4(ah, sb + T_WH + a_off[mt] + (col ^ a_key[mt]));
#pragma unroll
                for (int j = 0; j < 4; j++) {
                    mma16816_h(acc16[mt][2 * j],     ah, bh[j][0], bh[j][2]);
                    mma16816_h(acc16[mt][2 * j + 1], ah, bh[j][1], bh[j][3]);
                }
            }
        }

        // promote fp16 partials into fp32 masters every 128 K (exact adds)
        if (ck & 1) {
#pragma unroll
            for (int mt = 0; mt < 4; mt++)
#pragma unroll
                for (int nt = 0; nt < 8; nt++) {
                    float2 f0 = __half22float2(
                        *reinterpret_cast<__half2*>(&acc16[mt][nt][0]));
                    float2 f1 = __half22float2(
                        *reinterpret_cast<__half2*>(&acc16[mt][nt][1]));
                    acc[mt][nt][0] += f0.x;  acc[mt][nt][1] += f0.y;
                    acc[mt][nt][2] += f1.x;  acc[mt][nt][3] += f1.y;
                    acc16[mt][nt][0] = 0u;   acc16[mt][nt][1] = 0u;
                }
        }
    }

    // ---- epilogue: half2 stores to g_T16[b][o][phase][px] ----
    const int g  = lid >> 2;
    const int tq = lid & 3;
    unsigned short* tb = g_T16 + (((size_t)b * COUT + o0) * 16 + phase) * NPX;
#pragma unroll
    for (int mt = 0; mt < 4; mt++) {
#pragma unroll
        for (int nt = 0; nt < 8; nt++) {
            int o  = mw * 64 + mt * 16 + g;
            int px = nw * 64 + nt * 8 + tq * 2;
            __half2 h0 = __floats2half2_rn(acc[mt][nt][0], acc[mt][nt][1]);
            __half2 h1 = __floats2half2_rn(acc[mt][nt][2], acc[mt][nt][3]);
            *reinterpret_cast<__half2*>(tb + (size_t)o * (16 * NPX) + px)       = h0;
            *reinterpret_cast<__half2*>(tb + (size_t)(o + 8) * (16 * NPX) + px) = h1;
        }
    }
}

// ============================================================================
// Pass 3: unshuffle g_T16[b][o][phase][px] -> out[b][o][h][w]
//   2 o-planes per block; contiguous 16KB fp16 read, swizzled fp32 smem.
// ============================================================================
__global__ __launch_bounds__(256)
void unshuffle_kernel(float* __restrict__ out) {
    __shared__ float s[2][4096];
    const int t  = threadIdx.x;
    const int o0 = (blockIdx.x & 255) * 2;
    const int b  = blockIdx.x >> 8;

    const uint4* src = reinterpret_cast<const uint4*>(
        g_T16 + ((size_t)b * COUT + o0) * (16 * NPX));
#pragma unroll
    for (int i = 0; i < 4; i++) {
        int gi    = t + i * 256;        // 0..1023 uint4 (8 halves each)
        int plane = gi >> 9;
        int gj    = gi & 511;
        int ph    = gj >> 5, e8 = gj & 31;
        uint4 v = src[gi];
        float2 p0 = __half22float2(*reinterpret_cast<__half2*>(&v.x));
        float2 p1 = __half22float2(*reinterpret_cast<__half2*>(&v.y));
        float2 p2 = __half22float2(*reinterpret_cast<__half2*>(&v.z));
        float2 p3 = __half22float2(*reinterpret_cast<__half2*>(&v.w));
        float4* s4 = reinterpret_cast<float4*>(s[plane]);
        int key = ph >> 2;
        s4[ph * 64 + ((e8 * 2)     ^ key)] = make_float4(p0.x, p0.y, p1.x, p1.y);
        s4[ph * 64 + ((e8 * 2 + 1) ^ key)] = make_float4(p2.x, p2.y, p3.x, p3.y);
    }
    __syncthreads();

    const int h  = t >> 2;
    const int wb = (t & 3) * 16;
    const int r  = h & 3;
    const int h4 = h >> 2;
#pragma unroll
    for (int oo = 0; oo < 2; oo++) {
        float* dst = out + ((size_t)(b * COUT + o0 + oo) * 64 + h) * 64 + wb;
#pragma unroll
        for (int k4 = 0; k4 < 4; k4++) {
            int w4 = (wb >> 2) + k4;
            int f4 = h4 * 4 + (w4 >> 2);
            int fs = (f4 ^ r) * 4 + (w4 & 3);
            float4 v;
            v.x = s[oo][(r * 4 + 0) * 256 + fs];
            v.y = s[oo][(r * 4 + 1) * 256 + fs];
            v.z = s[oo][(r * 4 + 2) * 256 + fs];
            v.w = s[oo][(r * 4 + 3) * 256 + fs];
            *reinterpret_cast<float4*>(dst + k4 * 4) = v;
        }
    }
}

// ============================================================================
extern "C" void kernel_launch(void* const* d_in, const int* in_sizes, int n_in,
                              void* d_out, int out_size)
{
    const float* x  = (const float*)d_in[0];   // [16, 512, 64, 64]
    const float* Wg = (const float*)d_in[1];   // [16, 512, 512]
    float* out = (float*)d_out;                // [16, 512, 64, 64]

    cudaFuncSetAttribute(gwlp_mma_kernel,
                         cudaFuncAttributeMaxDynamicSharedMemorySize, 4 * STAGE_BYTES);

    convert_w_kernel<<<2048, 256>>>(Wg);
    convert_x_kernel<<<8192, 256>>>(x);
    gwlp_mma_kernel<<<1024, 256, 4 * STAGE_BYTES>>>();
    unshuffle_kernel<<<4096, 256>>>(out);
}

// round 9
// speedup vs baseline: 1.9337x; 1.0223x over previous
#include <cuda_runtime.h>
#include <cuda_fp16.h>
#include <cstdint>

// ============================================================================
// GroupWiseLinearProjector via single-pass fp16 mma.sync GEMM (compute_103)
//   out[b,o,h,w] = sum_c x[b,c,h,w] * Wg[p(h,w),o,c],  p=(h%4)*4+(w%4)
// Per (b,phase): D[512 o, 256 px] = W[512,512] * X[256 px, 512]^T
// R9: 16 warps (4/SMSP) to break per-warp HMMA serialization; 32x64 warp
//     tiles; fp32 accumulators; fp16 scratch + R8 unshuffle.
// ============================================================================

#define B_   16
#define CIN  512
#define COUT 512
#define NPX  256
#define KC   64          // K chunk (64 fp16 = 128B row, SW128 swizzle)
#define NSTAGE 8         // 512 / 64

// ---------------- scratch (device globals; no allocation) ----------------
__device__ __align__(256) unsigned short g_Xh[B_ * 16 * NPX * CIN];    // 64MB
__device__ __align__(256) unsigned short g_Wh[16 * COUT * CIN];        // 8MB
__device__ __align__(256) unsigned short g_T16[B_ * COUT * 16 * NPX];  // 67MB

// ---------------- helpers ----------------
__device__ __forceinline__ uint32_t smem_to_u32(const void* p) {
    uint32_t a;
    asm("{ .reg .u64 t; cvta.to.shared.u64 t, %1; cvt.u32.u64 %0, t; }"
        : "=r"(a) : "l"(p));
    return a;
}
__device__ __forceinline__ void cp_async16(uint32_t dst, const void* src) {
    asm volatile("cp.async.cg.shared.global [%0], [%1], 16;"
                 :: "r"(dst), "l"(src) : "memory");
}
#define CP_COMMIT() asm volatile("cp.async.commit_group;" ::: "memory")
#define CP_WAIT(n)  asm volatile("cp.async.wait_group %0;" :: "n"(n) : "memory")

__device__ __forceinline__ void ldmx4(uint32_t* r, uint32_t addr) {
    asm volatile("ldmatrix.sync.aligned.m8n8.x4.shared.b16 {%0,%1,%2,%3}, [%4];"
                 : "=r"(r[0]), "=r"(r[1]), "=r"(r[2]), "=r"(r[3]) : "r"(addr));
}
__device__ __forceinline__ void mma16816(float* d, const uint32_t* a,
                                         uint32_t b0, uint32_t b1) {
    asm volatile(
        "mma.sync.aligned.m16n8k16.row.col.f32.f16.f16.f32 "
        "{%0,%1,%2,%3}, {%4,%5,%6,%7}, {%8,%9}, {%0,%1,%2,%3};"
        : "+f"(d[0]), "+f"(d[1]), "+f"(d[2]), "+f"(d[3])
        : "r"(a[0]), "r"(a[1]), "r"(a[2]), "r"(a[3]), "r"(b0), "r"(b1));
}
#define SWZ(off) ((uint32_t)(off) ^ ((((uint32_t)(off)) >> 3) & 0x70))

// ============================================================================
// Pass 1a: W -> fp16 (layout [ph][o][c])
// ============================================================================
__global__ __launch_bounds__(256)
void convert_w_kernel(const float* __restrict__ Wg) {
    size_t gt = (size_t)blockIdx.x * 256 + threadIdx.x;
    const float4* src = reinterpret_cast<const float4*>(Wg) + gt * 2;
    float4 a = src[0], b = src[1];
    float v[8] = {a.x, a.y, a.z, a.w, b.x, b.y, b.z, b.w};
    unsigned short hb[8];
#pragma unroll
    for (int i = 0; i < 8; i++)
        hb[i] = __half_as_ushort(__float2half_rn(v[i]));
    uint4 uh;
    uh.x = hb[0] | (uint32_t)hb[1] << 16;  uh.y = hb[2] | (uint32_t)hb[3] << 16;
    uh.z = hb[4] | (uint32_t)hb[5] << 16;  uh.w = hb[6] | (uint32_t)hb[7] << 16;
    *reinterpret_cast<uint4*>(g_Wh + gt * 8) = uh;
}

// ============================================================================
// Pass 1b: x -> fp16 in [b][phase][px][c] (K-major)
// ============================================================================
__global__ __launch_bounds__(256)
void convert_x_kernel(const float* __restrict__ x) {
    __shared__ float sin[64][68];
    int bid = blockIdx.x;                 // 16 * 64 * 8 = 8192
    int cc = bid & 7;
    int h  = (bid >> 3) & 63;
    int b  = bid >> 9;
    int c0 = cc * 64;
    int t  = threadIdx.x;

    const float* src = x + (((size_t)b * CIN + c0) * 64 + h) * 64;
    {
        int c  = t >> 2;
        int f0 = t & 3;
#pragma unroll
        for (int j = 0; j < 4; j++) {
            float4 v = *reinterpret_cast<const float4*>(src + (size_t)c * 4096 + (f0 + 4 * j) * 4);
            *reinterpret_cast<float4*>(&sin[c][(f0 + 4 * j) * 4]) = v;
        }
    }
    __syncthreads();

    int p   = t >> 2;
    int q   = p >> 4;
    int w4  = p & 15;
    int cc4 = t & 3;
    int r   = h & 3;
    int h4  = h >> 2;

    unsigned short hb[16];
#pragma unroll
    for (int i = 0; i < 16; i++)
        hb[i] = __half_as_ushort(__float2half_rn(sin[cc4 * 16 + i][q + 4 * w4]));

    int phase = r * 4 + q;
    int px    = h4 * 16 + w4;
    size_t off = (((size_t)(b * 16 + phase) * NPX) + px) * CIN + c0 + cc4 * 16;

    uint4 u0, u1;
    u0.x = hb[0] | (uint32_t)hb[1] << 16;   u0.y = hb[2]  | (uint32_t)hb[3] << 16;
    u0.z = hb[4] | (uint32_t)hb[5] << 16;   u0.w = hb[6]  | (uint32_t)hb[7] << 16;
    u1.x = hb[8] | (uint32_t)hb[9] << 16;   u1.y = hb[10] | (uint32_t)hb[11] << 16;
    u1.z = hb[12]| (uint32_t)hb[13] << 16;  u1.w = hb[14] | (uint32_t)hb[15] << 16;
    *reinterpret_cast<uint4*>(g_Xh + off)     = u0;
    *reinterpret_cast<uint4*>(g_Xh + off + 8) = u1;
}

// ============================================================================
// Pass 2: GEMM, CTA = 128o x 256px, 512 threads, 16 warps of 32x64.
//   mw = wid&3 (32 o-rows), nw = wid>>2 (64 px); 4 warps/SMSP.
//   stage (48KB): Wh 16K | Xh 32K  (128B rows, SW128); 4 stages = 192KB
// ============================================================================
#define STAGE_BYTES 49152
#define T_WH 0
#define T_XH 16384

__global__ __launch_bounds__(512, 1)
void gwlp_mma_kernel() {
    extern __shared__ __align__(1024) char sm[];
    const uint32_t smb = smem_to_u32(sm);

    const int t   = threadIdx.x;
    const int wid = t >> 5;
    const int lid = t & 31;
    const int mw  = wid & 3;    // o sub-tile (32 rows)
    const int nw  = wid >> 2;   // px sub-tile (64 rows)

    const int bid   = blockIdx.x;   // 1024; otile fastest -> X shared via L2
    const int otile = bid & 3;
    const int phase = (bid >> 2) & 15;
    const int b     = bid >> 6;
    const int o0    = otile * 128;

    const unsigned short* whp = g_Wh + ((size_t)phase * COUT + o0) * CIN;
    const unsigned short* xhp = g_Xh + (size_t)(b * 16 + phase) * NPX * CIN;

    // ---- stage loader: 6 x 16B cp.async per thread ----
    auto load_stage = [&](int s, int buf) {
        const uint32_t sb = smb + (uint32_t)buf * STAGE_BYTES;
        const int ce = s * KC;
#pragma unroll
        for (int i = 0; i < 2; i++) {      // W: 1024 granules (128 rows x 8)
            int gi  = t + i * 512;
            int row = gi >> 3, g = gi & 7;
            uint32_t d = sb + SWZ(row * 128 + g * 16);
            cp_async16(d + T_WH, whp + (size_t)row * CIN + ce + g * 8);
        }
#pragma unroll
        for (int i = 0; i < 4; i++) {      // X: 2048 granules (256 rows x 8)
            int gi  = t + i * 512;
            int row = gi >> 3, g = gi & 7;
            uint32_t d = sb + SWZ(row * 128 + g * 16);
            cp_async16(d + T_XH, xhp + (size_t)row * CIN + ce + g * 8);
        }
        CP_COMMIT();
    };

    // ---- per-lane ldmatrix address components ----
    const int lr = lid & 15;
    const int cb = lid >> 4;
    uint32_t a_off[2], a_key[2];
#pragma unroll
    for (int mt = 0; mt < 2; mt++) {
        int row = mw * 32 + mt * 16 + lr;
        a_off[mt] = (uint32_t)row * 128;
        a_key[mt] = (uint32_t)(row & 7) << 4;
    }
    uint32_t b_off[4], b_key[4];
#pragma unroll
    for (int j = 0; j < 4; j++) {
        int row = nw * 64 + j * 16 + lr;
        b_off[j] = (uint32_t)row * 128;
        b_key[j] = (uint32_t)(row & 7) << 4;
    }

    float acc[2][8][4];
#pragma unroll
    for (int mt = 0; mt < 2; mt++)
#pragma unroll
        for (int nt = 0; nt < 8; nt++)
#pragma unroll
            for (int e = 0; e < 4; e++)
                acc[mt][nt][e] = 0.0f;

    // ---- 4-stage pipeline, single sync per stage ----
    load_stage(0, 0);
    load_stage(1, 1);
    load_stage(2, 2);

#pragma unroll 1
    for (int ck = 0; ck < NSTAGE; ck++) {
        if (ck < NSTAGE - 2)       { CP_WAIT(2); }
        else if (ck == NSTAGE - 2) { CP_WAIT(1); }
        else                       { CP_WAIT(0); }
        __syncthreads();
        {
            int nb = ck + 3;
            if (nb < NSTAGE) load_stage(nb, nb & 3);
        }

        const uint32_t sb = smb + (uint32_t)(ck & 3) * STAGE_BYTES;
#pragma unroll
        for (int ks = 0; ks < 4; ks++) {
            const uint32_t col = (uint32_t)(ks * 32 + cb * 16);
            uint32_t bh[4][4];
#pragma unroll
            for (int j = 0; j < 4; j++)
                ldmx4(bh[j], sb + T_XH + b_off[j] + (col ^ b_key[j]));
#pragma unroll
            for (int mt = 0; mt < 2; mt++) {
                uint32_t ah[4];
                ldmx4(ah, sb + T_WH + a_off[mt] + (col ^ a_key[mt]));
#pragma unroll
                for (int j = 0; j < 4; j++) {
                    mma16816(acc[mt][2 * j],     ah, bh[j][0], bh[j][2]);
                    mma16816(acc[mt][2 * j + 1], ah, bh[j][1], bh[j][3]);
                }
            }
        }
    }

    // ---- epilogue: half2 stores to g_T16[b][o][phase][px] ----
    const int g  = lid >> 2;
    const int tq = lid & 3;
    unsigned short* tb = g_T16 + (((size_t)b * COUT + o0) * 16 + phase) * NPX;
#pragma unroll
    for (int mt = 0; mt < 2; mt++) {
#pragma unroll
        for (int nt = 0; nt < 8; nt++) {
            int o  = mw * 32 + mt * 16 + g;
            int px = nw * 64 + nt * 8 + tq * 2;
            __half2 h0 = __floats2half2_rn(acc[mt][nt][0], acc[mt][nt][1]);
            __half2 h1 = __floats2half2_rn(acc[mt][nt][2], acc[mt][nt][3]);
            *reinterpret_cast<__half2*>(tb + (size_t)o * (16 * NPX) + px)       = h0;
            *reinterpret_cast<__half2*>(tb + (size_t)(o + 8) * (16 * NPX) + px) = h1;
        }
    }
}

// ============================================================================
// Pass 3: unshuffle g_T16[b][o][phase][px] -> out[b][o][h][w]
//   2 o-planes per block; contiguous 16KB fp16 read, swizzled fp32 smem.
// ============================================================================
__global__ __launch_bounds__(256)
void unshuffle_kernel(float* __restrict__ out) {
    __shared__ float s[2][4096];
    const int t  = threadIdx.x;
    const int o0 = (blockIdx.x & 255) * 2;
    const int b  = blockIdx.x >> 8;

    const uint4* src = reinterpret_cast<const uint4*>(
        g_T16 + ((size_t)b * COUT + o0) * (16 * NPX));
#pragma unroll
    for (int i = 0; i < 4; i++) {
        int gi    = t + i * 256;        // 0..1023 uint4 (8 halves each)
        int plane = gi >> 9;
        int gj    = gi & 511;
        int ph    = gj >> 5, e8 = gj & 31;
        uint4 v = src[gi];
        float2 p0 = __half22float2(*reinterpret_cast<__half2*>(&v.x));
        float2 p1 = __half22float2(*reinterpret_cast<__half2*>(&v.y));
        float2 p2 = __half22float2(*reinterpret_cast<__half2*>(&v.z));
        float2 p3 = __half22float2(*reinterpret_cast<__half2*>(&v.w));
        float4* s4 = reinterpret_cast<float4*>(s[plane]);
        int key = ph >> 2;
        s4[ph * 64 + ((e8 * 2)     ^ key)] = make_float4(p0.x, p0.y, p1.x, p1.y);
        s4[ph * 64 + ((e8 * 2 + 1) ^ key)] = make_float4(p2.x, p2.y, p3.x, p3.y);
    }
    __syncthreads();

    const int h  = t >> 2;
    const int wb = (t & 3) * 16;
    const int r  = h & 3;
    const int h4 = h >> 2;
#pragma unroll
    for (int oo = 0; oo < 2; oo++) {
        float* dst = out + ((size_t)(b * COUT + o0 + oo) * 64 + h) * 64 + wb;
#pragma unroll
        for (int k4 = 0; k4 < 4; k4++) {
            int w4 = (wb >> 2) + k4;
            int f4 = h4 * 4 + (w4 >> 2);
            int fs = (f4 ^ r) * 4 + (w4 & 3);
            float4 v;
            v.x = s[oo][(r * 4 + 0) * 256 + fs];
            v.y = s[oo][(r * 4 + 1) * 256 + fs];
            v.z = s[oo][(r * 4 + 2) * 256 + fs];
            v.w = s[oo][(r * 4 + 3) * 256 + fs];
            *reinterpret_cast<float4*>(dst + k4 * 4) = v;
        }
    }
}

// ============================================================================
extern "C" void kernel_launch(void* const* d_in, const int* in_sizes, int n_in,
                              void* d_out, int out_size)
{
    const float* x  = (const float*)d_in[0];   // [16, 512, 64, 64]
    const float* Wg = (const float*)d_in[1];   // [16, 512, 512]
    float* out = (float*)d_out;                // [16, 512, 64, 64]

    cudaFuncSetAttribute(gwlp_mma_kernel,
                         cudaFuncAttributeMaxDynamicSharedMemorySize, 4 * STAGE_BYTES);

    convert_w_kernel<<<2048, 256>>>(Wg);
    convert_x_kernel<<<8192, 256>>>(x);
    gwlp_mma_kernel<<<1024, 512, 4 * STAGE_BYTES>>>();
    unshuffle_kernel<<<4096, 256>>>(out);
}

// round 10
// speedup vs baseline: 1.9883x; 1.0283x over previous
#include <cuda_runtime.h>
#include <cuda_fp16.h>
#include <cstdint>

// ============================================================================
// GroupWiseLinearProjector via single-pass fp16 mma.sync GEMM (compute_103)
//   out[b,o,h,w] = sum_c x[b,c,h,w] * Wg[p(h,w),o,c],  p=(h%4)*4+(w%4)
// R10: CTA owns all 4 q-phases of one r (4 sub-GEMMs) so output rows are
//      full 64-wide w lines -> direct coalesced STG.128 epilogue.
//      No g_T16 scratch, no unshuffle kernel.
// ============================================================================

#define B_   16
#define CIN  512
#define COUT 512
#define NPX  256
#define KC   64          // K chunk (64 fp16 = 128B row, SW128 swizzle)
#define NSTAGE 8         // 512 / 64

// ---------------- scratch (device globals; no allocation) ----------------
__device__ __align__(256) unsigned short g_Xh[B_ * 16 * NPX * CIN];    // 64MB
__device__ __align__(256) unsigned short g_Wh[16 * COUT * CIN];        // 8MB

// ---------------- helpers ----------------
__device__ __forceinline__ uint32_t smem_to_u32(const void* p) {
    uint32_t a;
    asm("{ .reg .u64 t; cvta.to.shared.u64 t, %1; cvt.u32.u64 %0, t; }"
        : "=r"(a) : "l"(p));
    return a;
}
__device__ __forceinline__ void cp_async16(uint32_t dst, const void* src) {
    asm volatile("cp.async.cg.shared.global [%0], [%1], 16;"
                 :: "r"(dst), "l"(src) : "memory");
}
#define CP_COMMIT() asm volatile("cp.async.commit_group;" ::: "memory")
#define CP_WAIT(n)  asm volatile("cp.async.wait_group %0;" :: "n"(n) : "memory")

__device__ __forceinline__ void ldmx4(uint32_t* r, uint32_t addr) {
    asm volatile("ldmatrix.sync.aligned.m8n8.x4.shared.b16 {%0,%1,%2,%3}, [%4];"
                 : "=r"(r[0]), "=r"(r[1]), "=r"(r[2]), "=r"(r[3]) : "r"(addr));
}
__device__ __forceinline__ void mma16816(float* d, const uint32_t* a,
                                         uint32_t b0, uint32_t b1) {
    asm volatile(
        "mma.sync.aligned.m16n8k16.row.col.f32.f16.f16.f32 "
        "{%0,%1,%2,%3}, {%4,%5,%6,%7}, {%8,%9}, {%0,%1,%2,%3};"
        : "+f"(d[0]), "+f"(d[1]), "+f"(d[2]), "+f"(d[3])
        : "r"(a[0]), "r"(a[1]), "r"(a[2]), "r"(a[3]), "r"(b0), "r"(b1));
}
#define SWZ(off) ((uint32_t)(off) ^ ((((uint32_t)(off)) >> 3) & 0x70))

// ============================================================================
// Pass 1a: W -> fp16 (layout [ph][o][c])
// ============================================================================
__global__ __launch_bounds__(256)
void convert_w_kernel(const float* __restrict__ Wg) {
    size_t gt = (size_t)blockIdx.x * 256 + threadIdx.x;
    const float4* src = reinterpret_cast<const float4*>(Wg) + gt * 2;
    float4 a = src[0], b = src[1];
    float v[8] = {a.x, a.y, a.z, a.w, b.x, b.y, b.z, b.w};
    unsigned short hb[8];
#pragma unroll
    for (int i = 0; i < 8; i++)
        hb[i] = __half_as_ushort(__float2half_rn(v[i]));
    uint4 uh;
    uh.x = hb[0] | (uint32_t)hb[1] << 16;  uh.y = hb[2] | (uint32_t)hb[3] << 16;
    uh.z = hb[4] | (uint32_t)hb[5] << 16;  uh.w = hb[6] | (uint32_t)hb[7] << 16;
    *reinterpret_cast<uint4*>(g_Wh + gt * 8) = uh;
}

// ============================================================================
// Pass 1b: x -> fp16 in [b][phase][px][c] (K-major)
// ============================================================================
__global__ __launch_bounds__(256)
void convert_x_kernel(const float* __restrict__ x) {
    __shared__ float sin[64][68];
    int bid = blockIdx.x;                 // 16 * 64 * 8 = 8192
    int cc = bid & 7;
    int h  = (bid >> 3) & 63;
    int b  = bid >> 9;
    int c0 = cc * 64;
    int t  = threadIdx.x;

    const float* src = x + (((size_t)b * CIN + c0) * 64 + h) * 64;
    {
        int c  = t >> 2;
        int f0 = t & 3;
#pragma unroll
        for (int j = 0; j < 4; j++) {
            float4 v = *reinterpret_cast<const float4*>(src + (size_t)c * 4096 + (f0 + 4 * j) * 4);
            *reinterpret_cast<float4*>(&sin[c][(f0 + 4 * j) * 4]) = v;
        }
    }
    __syncthreads();

    int p   = t >> 2;
    int q   = p >> 4;
    int w4  = p & 15;
    int cc4 = t & 3;
    int r   = h & 3;
    int h4  = h >> 2;

    unsigned short hb[16];
#pragma unroll
    for (int i = 0; i < 16; i++)
        hb[i] = __half_as_ushort(__float2half_rn(sin[cc4 * 16 + i][q + 4 * w4]));

    int phase = r * 4 + q;
    int px    = h4 * 16 + w4;
    size_t off = (((size_t)(b * 16 + phase) * NPX) + px) * CIN + c0 + cc4 * 16;

    uint4 u0, u1;
    u0.x = hb[0] | (uint32_t)hb[1] << 16;   u0.y = hb[2]  | (uint32_t)hb[3] << 16;
    u0.z = hb[4] | (uint32_t)hb[5] << 16;   u0.w = hb[6]  | (uint32_t)hb[7] << 16;
    u1.x = hb[8] | (uint32_t)hb[9] << 16;   u1.y = hb[10] | (uint32_t)hb[11] << 16;
    u1.z = hb[12]| (uint32_t)hb[13] << 16;  u1.w = hb[14] | (uint32_t)hb[15] << 16;
    *reinterpret_cast<uint4*>(g_Xh + off)     = u0;
    *reinterpret_cast<uint4*>(g_Xh + off + 8) = u1;
}

// ============================================================================
// Pass 2: fused GEMM+unshuffle.
//   CTA = (b, r, otile 128o, ht h4-tile): 4 sub-GEMMs (q=0..3), each
//   128o x 64px, K=512. 512 threads; warp = (q = wid&3, oq = wid>>2).
//   Stage (96KB): W[q] 4x16KB | X[q] 4x8KB; double-buffered = 192KB.
//   Epilogue: acc -> smem (68-float rows) -> coalesced STG.128 to out.
// ============================================================================
#define STAGE_BYTES 98304
#define XOFF 65536

__global__ __launch_bounds__(512, 1)
void gwlp_mma_kernel(float* __restrict__ out) {
    extern __shared__ __align__(1024) char sm[];
    const uint32_t smb = smem_to_u32(sm);

    const int t   = threadIdx.x;
    const int wid = t >> 5;
    const int lid = t & 31;
    const int q   = wid & 3;    // phase column of this warp
    const int oq  = wid >> 2;   // o quarter (32 rows)

    const int bid   = blockIdx.x;   // 1024: ht fastest (share W,X in L2)
    const int ht    = bid & 3;
    const int otile = (bid >> 2) & 3;
    const int r     = (bid >> 4) & 3;
    const int b     = bid >> 6;
    const int o0    = otile * 128;
    const int px0   = ht * 64;

    const unsigned short* whp0 = g_Wh + ((size_t)(r * 4) * COUT + o0) * CIN;
    const unsigned short* xhp0 = g_Xh + ((size_t)(b * 16 + r * 4) * NPX + px0) * CIN;

    // ---- stage loader: 12 x 16B cp.async per thread ----
    auto load_stage = [&](int s, int buf) {
        const uint32_t sb = smb + (uint32_t)buf * STAGE_BYTES;
        const int ce = s * KC;
#pragma unroll
        for (int i = 0; i < 8; i++) {      // W: 4096 granules (4q x 128 x 8)
            int gi  = t + i * 512;
            int lq  = gi >> 10;
            int wi  = gi & 1023;
            int row = wi >> 3, g = wi & 7;
            uint32_t d = sb + lq * 16384 + SWZ(row * 128 + g * 16);
            cp_async16(d, whp0 + (size_t)lq * (COUT * CIN) + (size_t)row * CIN + ce + g * 8);
        }
#pragma unroll
        for (int i = 0; i < 4; i++) {      // X: 2048 granules (4q x 64 x 8)
            int gi  = t + i * 512;
            int lq  = gi >> 9;
            int wi  = gi & 511;
            int row = wi >> 3, g = wi & 7;
            uint32_t d = sb + XOFF + lq * 8192 + SWZ(row * 128 + g * 16);
            cp_async16(d, xhp0 + (size_t)lq * (NPX * CIN) + (size_t)row * CIN + ce + g * 8);
        }
        CP_COMMIT();
    };

    // ---- per-lane ldmatrix address components ----
    const int lr = lid & 15;
    const int cb = lid >> 4;
    const uint32_t wq_off = (uint32_t)q * 16384;
    const uint32_t xq_off = XOFF + (uint32_t)q * 8192;
    uint32_t a_off[2], a_key[2];
#pragma unroll
    for (int mt = 0; mt < 2; mt++) {
        int row = oq * 32 + mt * 16 + lr;
        a_off[mt] = (uint32_t)row * 128;
        a_key[mt] = (uint32_t)(row & 7) << 4;
    }
    uint32_t b_off[4], b_key[4];
#pragma unroll
    for (int j = 0; j < 4; j++) {
        int row = j * 16 + lr;              // px rows 0..63
        b_off[j] = (uint32_t)row * 128;
        b_key[j] = (uint32_t)(row & 7) << 4;
    }

    float acc[2][8][4];
#pragma unroll
    for (int mt = 0; mt < 2; mt++)
#pragma unroll
        for (int nt = 0; nt < 8; nt++)
#pragma unroll
            for (int e = 0; e < 4; e++)
                acc[mt][nt][e] = 0.0f;

    // ---- 2-stage pipeline (R3-proven loop) ----
    load_stage(0, 0);
    load_stage(1, 1);

#pragma unroll 1
    for (int ck = 0; ck < NSTAGE; ck++) {
        if (ck == NSTAGE - 1) { CP_WAIT(0); } else { CP_WAIT(1); }
        __syncthreads();

        const uint32_t sb = smb + (uint32_t)(ck & 1) * STAGE_BYTES;
#pragma unroll
        for (int ks = 0; ks < 4; ks++) {
            const uint32_t col = (uint32_t)(ks * 32 + cb * 16);
            uint32_t bh[4][4];
#pragma unroll
            for (int j = 0; j < 4; j++)
                ldmx4(bh[j], sb + xq_off + b_off[j] + (col ^ b_key[j]));
#pragma unroll
            for (int mt = 0; mt < 2; mt++) {
                uint32_t ah[4];
                ldmx4(ah, sb + wq_off + a_off[mt] + (col ^ a_key[mt]));
#pragma unroll
                for (int j = 0; j < 4; j++) {
                    mma16816(acc[mt][2 * j],     ah, bh[j][0], bh[j][2]);
                    mma16816(acc[mt][2 * j + 1], ah, bh[j][1], bh[j][3]);
                }
            }
        }
        __syncthreads();
        if (ck + 2 < NSTAGE) load_stage(ck + 2, ck & 1);
    }

    // ---- fused epilogue: acc -> smem rows -> coalesced out stores ----
    // S: 512 rows (o_local*4 + h4l) x 68 floats (64 w + 4 pad; 16B-aligned)
    __syncthreads();
    float* S = reinterpret_cast<float*>(sm);
    {
        const int g  = lid >> 2;
        const int tq = lid & 3;
#pragma unroll
        for (int mt = 0; mt < 2; mt++) {
#pragma unroll
            for (int nt = 0; nt < 8; nt++) {
                int px  = nt * 8 + tq * 2;      // local px (0..63)
                int h4l = px >> 4;
                int w4  = px & 15;
                int w0  = 4 * w4 + q;
                int o_lo = oq * 32 + mt * 16 + g;
                int R0 = (o_lo)     * 4 + h4l;
                int R1 = (o_lo + 8) * 4 + h4l;
                S[R0 * 68 + w0]     = acc[mt][nt][0];
                S[R0 * 68 + w0 + 4] = acc[mt][nt][1];
                S[R1 * 68 + w0]     = acc[mt][nt][2];
                S[R1 * 68 + w0 + 4] = acc[mt][nt][3];
            }
        }
    }
    __syncthreads();

    // stores: 512 rows x 64 floats; lane half-warps cover 2 full 256B rows.
    {
        const int f4  = t & 15;
        const int rl0 = t >> 4;                 // 0..31
#pragma unroll
        for (int p = 0; p < 16; p++) {
            int rowid = p * 32 + rl0;           // 0..511
            int o    = rowid >> 2;
            int h4l  = rowid & 3;
            int h    = 16 * ht + 4 * h4l + r;
            float4 v = *reinterpret_cast<const float4*>(&S[rowid * 68 + f4 * 4]);
            float* dst = out + (((size_t)b * COUT + o0 + o) * 64 + h) * 64 + f4 * 4;
            *reinterpret_cast<float4*>(dst) = v;
        }
    }
}

// ============================================================================
extern "C" void kernel_launch(void* const* d_in, const int* in_sizes, int n_in,
                              void* d_out, int out_size)
{
    const float* x  = (const float*)d_in[0];   // [16, 512, 64, 64]
    const float* Wg = (const float*)d_in[1];   // [16, 512, 512]
    float* out = (float*)d_out;                // [16, 512, 64, 64]

    cudaFuncSetAttribute(gwlp_mma_kernel,
                         cudaFuncAttributeMaxDynamicSharedMemorySize, 2 * STAGE_BYTES);

    convert_w_kernel<<<2048, 256>>>(Wg);
    convert_x_kernel<<<8192, 256>>>(x);
    gwlp_mma_kernel<<<1024, 512, 2 * STAGE_BYTES>>>(out);
}